// round 11
// baseline (speedup 1.0000x reference)
#include <cuda_runtime.h>
#include <cuda_fp16.h>
#include <cuda_bf16.h>

#define B 8
#define T 1024
#define D 512
#define H 8
#define DK 64
#define BT (B*T)   // 8192

// Scratch (static device globals — no runtime allocation)
__device__ __half g_x16[4][BT * D];          // fp16 copies of query/key/value/pos
__device__ unsigned g_w16[5][D * D / 2];     // k-paired half2 weights
__device__ __half g_q16[BT * D];
__device__ __half g_k16[BT * D];
__device__ __half g_v16[BT * D];
__device__ __half g_p16[BT * D];
__device__ __half g_v16i[BT * D];            // [bh][t/2][d] k-paired half2 words
__device__ __nv_bfloat16 g_cs[(size_t)B * H * T * T];
__device__ __nv_bfloat16 g_ps[(size_t)B * H * T * T];
__device__ __half g_ctx16[BT * D];

__device__ __forceinline__ unsigned packh2(float lo, float hi) {
    __half2 h = __floats2half2_rn(lo, hi);
    return *(unsigned*)&h;
}
__device__ __forceinline__ float2 unpackh2(unsigned u) {
    __half2 h = *(__half2*)&u;
    return __half22float2(h);
}

// mma.sync m16n8k16 f16 row.col, fp32 accumulate
__device__ __forceinline__ void mma_f16(float* c, unsigned a0, unsigned a1,
                                        unsigned a2, unsigned a3,
                                        unsigned b0, unsigned b1) {
    asm volatile(
        "mma.sync.aligned.m16n8k16.row.col.f32.f16.f16.f32 "
        "{%0,%1,%2,%3}, {%4,%5,%6,%7}, {%8,%9}, {%0,%1,%2,%3};"
        : "+f"(c[0]), "+f"(c[1]), "+f"(c[2]), "+f"(c[3])
        : "r"(a0), "r"(a1), "r"(a2), "r"(a3), "r"(b0), "r"(b1));
}

__device__ __forceinline__ void cp16g(void* dst, const void* src) {
    unsigned d = (unsigned)__cvta_generic_to_shared(dst);
    asm volatile("cp.async.ca.shared.global [%0], [%1], 16;" :: "r"(d), "l"(src));
}
__device__ __forceinline__ void cp_commit() { asm volatile("cp.async.commit_group;"); }
__device__ __forceinline__ void cp_wait1()  { asm volatile("cp.async.wait_group 1;"); }
__device__ __forceinline__ void cp_wait0()  { asm volatile("cp.async.wait_group 0;"); }

__device__ __forceinline__ float bf2f(unsigned short u) {
    return __uint_as_float(((unsigned)u) << 16);
}

// ---------------------------------------------------------------------------
// One-time conversions
// ---------------------------------------------------------------------------
struct ActPtrs { const float* in[4]; __half* out[4]; };

__global__ __launch_bounds__(256) void cvt_act(ActPtrs ap)
{
    int z = blockIdx.y;
    const float* in = ap.in[z];
    __half* out = ap.out[z];
    size_t i = ((size_t)blockIdx.x * 256 + threadIdx.x) * 8;
    float4 a = *(const float4*)&in[i];
    float4 b = *(const float4*)&in[i + 4];
    uint4 o;
    o.x = packh2(a.x, a.y); o.y = packh2(a.z, a.w);
    o.z = packh2(b.x, b.y); o.w = packh2(b.z, b.w);
    *(uint4*)&out[i] = o;
}

struct WPtrs { const float* in[5]; unsigned* out[5]; };

__global__ __launch_bounds__(256) void cvt_w(WPtrs wp)
{
    int z = blockIdx.y;
    const float* W = wp.in[z];
    unsigned* O = wp.out[z];
    int idx = blockIdx.x * 256 + threadIdx.x;
    int kp = idx >> 7, n4 = (idx & 127) * 4;
    float4 w0 = *(const float4*)&W[(size_t)(2 * kp) * D + n4];
    float4 w1 = *(const float4*)&W[(size_t)(2 * kp + 1) * D + n4];
    uint4 o;
    o.x = packh2(w0.x, w1.x); o.y = packh2(w0.y, w1.y);
    o.z = packh2(w0.z, w1.z); o.w = packh2(w0.w, w1.w);
    *(uint4*)&O[(size_t)kp * D + n4] = o;
}

// ---------------------------------------------------------------------------
// GEMM (all fp16, cp.async 3-stage): C = A[M,512]@W[512,512] + bias.
// ---------------------------------------------------------------------------
struct GArgs {
    const __half* A[5];
    const unsigned* W[5];
    const float* bias[5];
    __half* Ch[5];
    float* Cf[5];
};

__global__ __launch_bounds__(256) void gemm_h16(GArgs ga, int base)
{
    const int N = D, K = D;
    int gi = base + blockIdx.z;
    const __half* A = ga.A[gi];
    const unsigned* W = ga.W[gi];
    const float* bias = ga.bias[gi];
    __half* Ch = ga.Ch[gi];
    float* Cf = ga.Cf[gi];

    extern __shared__ unsigned sm[];
    unsigned* As = sm;
    unsigned* Ws = sm + 3 * 128 * 20;

    int tid = threadIdx.x, warp = tid >> 5, lane = tid & 31;
    int gid = lane >> 2, tig = lane & 3;
    int wm = warp & 1, wn = warp >> 1;
    int bm = blockIdx.y * 128, bn = blockIdx.x * 128;

    const int nsteps = K / 32;

    int arow0 = tid >> 2, ac0 = tid & 3;
    int arow1 = arow0 + 64;
    int wkk0 = tid >> 5, wc0 = tid & 31;
    int wkk1 = wkk0 + 8;

    #pragma unroll
    for (int s = 0; s < 2; s++) {
        int k0 = s * 32;
        unsigned* as = As + (s % 3) * (128 * 20);
        unsigned* ws = Ws + (s % 3) * (16 * 136);
        cp16g(as + arow0 * 20 + ac0 * 4, A + (size_t)(bm + arow0) * K + k0 + ac0 * 8);
        cp16g(as + arow1 * 20 + ac0 * 4, A + (size_t)(bm + arow1) * K + k0 + ac0 * 8);
        cp16g(ws + wkk0 * 136 + wc0 * 4, W + (size_t)(k0 / 2 + wkk0) * N + bn + wc0 * 4);
        cp16g(ws + wkk1 * 136 + wc0 * 4, W + (size_t)(k0 / 2 + wkk1) * N + bn + wc0 * 4);
        cp_commit();
    }

    float acc[4][4][4] = {};
    for (int s = 0; s < nsteps; s++) {
        cp_wait1();
        __syncthreads();
        int st = s % 3;
        if (s + 2 < nsteps) {
            int k0 = (s + 2) * 32, st2 = (s + 2) % 3;
            unsigned* as = As + st2 * (128 * 20);
            unsigned* ws = Ws + st2 * (16 * 136);
            cp16g(as + arow0 * 20 + ac0 * 4, A + (size_t)(bm + arow0) * K + k0 + ac0 * 8);
            cp16g(as + arow1 * 20 + ac0 * 4, A + (size_t)(bm + arow1) * K + k0 + ac0 * 8);
            cp16g(ws + wkk0 * 136 + wc0 * 4, W + (size_t)(k0 / 2 + wkk0) * N + bn + wc0 * 4);
            cp16g(ws + wkk1 * 136 + wc0 * 4, W + (size_t)(k0 / 2 + wkk1) * N + bn + wc0 * 4);
        }
        cp_commit();

        const unsigned* as = As + st * (128 * 20);
        const unsigned* ws = Ws + st * (16 * 136);
        #pragma unroll
        for (int ks = 0; ks < 2; ks++) {
            unsigned af[4][4], bf[4][2];
            #pragma unroll
            for (int mt = 0; mt < 4; mt++) {
                int r = wm * 64 + mt * 16 + gid;
                af[mt][0] = as[r * 20 + ks * 8 + tig];
                af[mt][1] = as[(r + 8) * 20 + ks * 8 + tig];
                af[mt][2] = as[r * 20 + ks * 8 + 4 + tig];
                af[mt][3] = as[(r + 8) * 20 + ks * 8 + 4 + tig];
            }
            #pragma unroll
            for (int nt = 0; nt < 4; nt++) {
                int c = wn * 32 + nt * 8 + gid;
                bf[nt][0] = ws[(ks * 8 + tig) * 136 + c];
                bf[nt][1] = ws[(ks * 8 + 4 + tig) * 136 + c];
            }
            #pragma unroll
            for (int mt = 0; mt < 4; mt++)
                #pragma unroll
                for (int nt = 0; nt < 4; nt++)
                    mma_f16(acc[mt][nt], af[mt][0], af[mt][1], af[mt][2], af[mt][3],
                            bf[nt][0], bf[nt][1]);
        }
    }

    #pragma unroll
    for (int mt = 0; mt < 4; mt++) {
        int r0 = bm + wm * 64 + mt * 16 + gid;
        #pragma unroll
        for (int nt = 0; nt < 4; nt++) {
            int c0 = bn + wn * 32 + nt * 8 + 2 * tig;
            float b0 = bias ? bias[c0] : 0.f;
            float b1 = bias ? bias[c0 + 1] : 0.f;
            float v0 = acc[mt][nt][0] + b0, v1 = acc[mt][nt][1] + b1;
            float v2 = acc[mt][nt][2] + b0, v3 = acc[mt][nt][3] + b1;
            if (Ch) {
                *(unsigned*)&Ch[(size_t)r0 * N + c0]       = packh2(v0, v1);
                *(unsigned*)&Ch[(size_t)(r0 + 8) * N + c0] = packh2(v2, v3);
            } else {
                Cf[(size_t)r0 * N + c0]           = v0;
                Cf[(size_t)r0 * N + c0 + 1]       = v1;
                Cf[(size_t)(r0 + 8) * N + c0]     = v2;
                Cf[(size_t)(r0 + 8) * N + c0 + 1] = v3;
            }
        }
    }
}

// ---------------------------------------------------------------------------
// V reshuffle: v16 [b][t][h][d] -> v16i [bh][t/2][d] k-paired half2 words.
// ---------------------------------------------------------------------------
__global__ __launch_bounds__(256) void v_reshape(
    const __half* __restrict__ v16, __half* __restrict__ v16i)
{
    int gidx = blockIdx.x * 256 + threadIdx.x;
    int d8 = gidx & 7;
    int rem = gidx >> 3;
    int kk = rem & 511;
    int bh = rem >> 9;
    int b = bh >> 3, h = bh & 7;

    uint4 x = *(const uint4*)(v16 + ((size_t)(b * T + 2 * kk) * H + h) * DK + d8 * 8);
    uint4 y = *(const uint4*)(v16 + ((size_t)(b * T + 2 * kk + 1) * H + h) * DK + d8 * 8);
    const unsigned short* xs = (const unsigned short*)&x;
    const unsigned short* ys = (const unsigned short*)&y;
    unsigned out[8];
    #pragma unroll
    for (int i = 0; i < 8; i++)
        out[i] = (unsigned)xs[i] | ((unsigned)ys[i] << 16);
    unsigned* dst = (unsigned*)v16i + ((size_t)bh * 512 + kk) * 64 + d8 * 8;
    *(uint4*)(dst + 0) = *(uint4*)(out + 0);
    *(uint4*)(dst + 4) = *(uint4*)(out + 4);
}

// ---------------------------------------------------------------------------
// Fused scores (fp16): cs = scale*(q+u)·k, ps = scale*(q+v)·p -> bf16.
// ---------------------------------------------------------------------------
#define QS 36
__device__ __forceinline__ void score_mma_bf16(
    const unsigned* __restrict__ Q, const unsigned* __restrict__ KP,
    __nv_bfloat16* __restrict__ out, size_t obase, int bi, int bj,
    int wm, int wn, int gid, int tig)
{
    float acc[4][4][4] = {};
    #pragma unroll
    for (int ks = 0; ks < 4; ks++) {
        unsigned af[4][4], bf[4][2];
        #pragma unroll
        for (int mt = 0; mt < 4; mt++) {
            int r = wm * 64 + mt * 16 + gid;
            af[mt][0] = Q[r * QS + ks * 8 + tig];
            af[mt][1] = Q[(r + 8) * QS + ks * 8 + tig];
            af[mt][2] = Q[r * QS + ks * 8 + 4 + tig];
            af[mt][3] = Q[(r + 8) * QS + ks * 8 + 4 + tig];
        }
        #pragma unroll
        for (int nt = 0; nt < 4; nt++) {
            int c = wn * 32 + nt * 8 + gid;
            bf[nt][0] = KP[c * QS + ks * 8 + tig];
            bf[nt][1] = KP[c * QS + ks * 8 + 4 + tig];
        }
        #pragma unroll
        for (int mt = 0; mt < 4; mt++)
            #pragma unroll
            for (int nt = 0; nt < 4; nt++)
                mma_f16(acc[mt][nt], af[mt][0], af[mt][1], af[mt][2], af[mt][3],
                        bf[nt][0], bf[nt][1]);
    }
    const float scale = 0.04419417382415922f;   // 1/sqrt(512)
    #pragma unroll
    for (int mt = 0; mt < 4; mt++) {
        int r0 = bi + wm * 64 + mt * 16 + gid;
        #pragma unroll
        for (int nt = 0; nt < 4; nt++) {
            int c0 = bj + wn * 32 + nt * 8 + 2 * tig;
            __nv_bfloat162 p0 = __floats2bfloat162_rn(acc[mt][nt][0] * scale,
                                                      acc[mt][nt][1] * scale);
            __nv_bfloat162 p1 = __floats2bfloat162_rn(acc[mt][nt][2] * scale,
                                                      acc[mt][nt][3] * scale);
            *(__nv_bfloat162*)&out[obase + (size_t)r0 * T + c0]       = p0;
            *(__nv_bfloat162*)&out[obase + (size_t)(r0 + 8) * T + c0] = p1;
        }
    }
}

__global__ __launch_bounds__(256) void score_fused_f16(
    const __half* __restrict__ q16, const __half* __restrict__ k16,
    const __half* __restrict__ p16, const float* __restrict__ ub,
    const float* __restrict__ vb,
    __nv_bfloat16* __restrict__ cs, __nv_bfloat16* __restrict__ ps)
{
    extern __shared__ unsigned smu[];
    unsigned* Qu = smu;
    unsigned* Qv = smu + 128 * QS;
    unsigned* KP = smu + 2 * 128 * QS;
    __shared__ float sub[DK], svb[DK];

    int bh = blockIdx.z, b = bh >> 3, h = bh & 7;
    int bi = blockIdx.y * 128, bj = blockIdx.x * 128;
    int tid = threadIdx.x, warp = tid >> 5, lane = tid & 31;
    int gid = lane >> 2, tig = lane & 3;
    int wm = warp & 1, wn = warp >> 1;
    size_t obase = (size_t)bh * T * T;

    if (tid < DK) {
        sub[tid] = ub[h * DK + tid];
        svb[tid] = vb[h * DK + tid];
    }

    #pragma unroll
    for (int l = 0; l < 4; l++) {
        int idx = tid + l * 256;
        int row = idx >> 3, c16 = idx & 7;
        cp16g((char*)KP + row * (QS * 4) + c16 * 16,
              k16 + ((size_t)(b * T + bj + row) * H + h) * DK + c16 * 8);
    }
    cp_commit();
    __syncthreads();

    {
        int row = tid >> 1, doff = (tid & 1) * 32;
        const uint4* qp = (const uint4*)(q16 + ((size_t)(b * T + bi + row) * H + h) * DK + doff);
        uint4 r4[4] = { qp[0], qp[1], qp[2], qp[3] };
        const unsigned* rw = (const unsigned*)r4;
        unsigned* qud = &Qu[row * QS + doff / 2];
        unsigned* qvd = &Qv[row * QS + doff / 2];
        #pragma unroll
        for (int u = 0; u < 16; u++) {
            float2 f = unpackh2(rw[u]);
            int d = doff + 2 * u;
            qud[u] = packh2(f.x + sub[d], f.y + sub[d + 1]);
            qvd[u] = packh2(f.x + svb[d], f.y + svb[d + 1]);
        }
    }
    cp_wait0();
    __syncthreads();

    score_mma_bf16(Qu, KP, cs, obase, bi, bj, wm, wn, gid, tig);
    __syncthreads();

    #pragma unroll
    for (int l = 0; l < 4; l++) {
        int idx = tid + l * 256;
        int row = idx >> 3, c16 = idx & 7;
        cp16g((char*)KP + row * (QS * 4) + c16 * 16,
              p16 + ((size_t)(b * T + bj + row) * H + h) * DK + c16 * 8);
    }
    cp_commit();
    cp_wait0();
    __syncthreads();

    score_mma_bf16(Qv, KP, ps, obase, bi, bj, wm, wn, gid, tig);
}

// ---------------------------------------------------------------------------
// Flash: fused rel-shift + online softmax + context.
// CTA = 128 query rows of one bh; streams 16 j-tiles of 64.
//   shifted[i,j] = (j<=i) ? ps[i, T+j-i-1] : (j==i+1) ? 0 : ps[i+1, j-i-2]
// Each thread owns half a row per tile (32 fp32 vals in regs); one shfl pair-
// reduce per row. S tile fp16 in smem feeds m16n8k16 MMA against V (k-paired).
// ---------------------------------------------------------------------------
__global__ __launch_bounds__(256, 2) void flash_ctx(
    const __nv_bfloat16* __restrict__ cs, const __nv_bfloat16* __restrict__ ps,
    const __half* __restrict__ v16i, __half* __restrict__ ctx16)
{
    __shared__ unsigned S[128 * 36];       // [row][32 words + 4 pad]
    __shared__ unsigned Vs[2][32 * 72];    // [kpair][64 d words + 8 pad]
    __shared__ float m_s[128], l_s[128], f_s[128];

    int bh = blockIdx.y, b = bh >> 3, h = bh & 7;
    int bi = blockIdx.x * 128;
    int tid = threadIdx.x, warp = tid >> 5, lane = tid & 31;
    int gid = lane >> 2, tig = lane & 3;
    int wm = warp >> 1, wn = warp & 1;     // 4x2 warps, warp tile 32x32
    size_t base = (size_t)bh * T * T;
    const unsigned* vsrc = (const unsigned*)v16i + (size_t)bh * 512 * 64;

    if (tid < 128) { m_s[tid] = -1e30f; l_s[tid] = 0.f; }

    // prefetch V tile 0 (32 kpairs x 64 words = 512 x 16B, 2 chunks/thread)
    {
        int i0 = tid, i1 = tid + 256;
        cp16g(&Vs[0][(i0 >> 4) * 72 + (i0 & 15) * 4], vsrc + (size_t)(i0 >> 4) * 64 + (i0 & 15) * 4);
        cp16g(&Vs[0][(i1 >> 4) * 72 + (i1 & 15) * 4], vsrc + (size_t)(i1 >> 4) * 64 + (i1 & 15) * 4);
        cp_commit();
    }

    float acc[2][4][4] = {};
    int r = tid >> 1, ch = tid & 1;
    int rg = bi + r;
    const int NT = T / 64;   // 16

    for (int jt = 0; jt < NT; jt++) {
        __syncthreads();   // prev MMA done with S and Vs[(jt+1)&1]

        if (jt + 1 < NT) {
            int kbase = (jt + 1) * 32, buf = (jt + 1) & 1;
            int i0 = tid, i1 = tid + 256;
            cp16g(&Vs[buf][(i0 >> 4) * 72 + (i0 & 15) * 4],
                  vsrc + (size_t)(kbase + (i0 >> 4)) * 64 + (i0 & 15) * 4);
            cp16g(&Vs[buf][(i1 >> 4) * 72 + (i1 & 15) * 4],
                  vsrc + (size_t)(kbase + (i1 >> 4)) * 64 + (i1 & 15) * 4);
            cp_commit();
        }

        // ---- softmax phase: thread owns row r, cols [jc, jc+32)
        int jc = jt * 64 + ch * 32;
        const unsigned short* crow = (const unsigned short*)(cs + base + (size_t)rg * T + jc);
        float vals[32];
        float mx = -1e30f;
        #pragma unroll
        for (int u = 0; u < 32; u++) {
            int j = jc + u;
            float pv;
            if (j <= rg)
                pv = bf2f(*(const unsigned short*)&ps[base + (size_t)rg * T + (T + j - rg - 1)]);
            else if (j == rg + 1)
                pv = 0.0f;
            else
                pv = bf2f(*(const unsigned short*)&ps[base + (size_t)(rg + 1) * T + (j - rg - 2)]);
            float s = bf2f(crow[u]) + pv;
            vals[u] = s;
            mx = fmaxf(mx, s);
        }
        mx = fmaxf(mx, __shfl_xor_sync(0xffffffffu, mx, 1));
        float m_old = m_s[r];
        float m_new = fmaxf(m_old, mx);
        float fct = __expf(m_old - m_new);
        float sum = 0.f;
        #pragma unroll
        for (int u = 0; u < 32; u++) {
            vals[u] = __expf(vals[u] - m_new);
            sum += vals[u];
        }
        sum += __shfl_xor_sync(0xffffffffu, sum, 1);
        if (ch == 0) {
            m_s[r] = m_new;
            l_s[r] = l_s[r] * fct + sum;
            f_s[r] = fct;
        }
        unsigned* srow = &S[r * 36 + ch * 16];
        #pragma unroll
        for (int u2 = 0; u2 < 16; u2++)
            srow[u2] = packh2(vals[2 * u2], vals[2 * u2 + 1]);

        if (jt + 1 < NT) cp_wait1(); else cp_wait0();
        __syncthreads();

        // ---- rescale + MMA:  acc = acc*f + S(128x64) @ V(64x64)
        int buf = jt & 1;
        #pragma unroll
        for (int mt = 0; mt < 2; mt++) {
            int rr = wm * 32 + mt * 16 + gid;
            float f1 = f_s[rr], f2 = f_s[rr + 8];
            #pragma unroll
            for (int nt = 0; nt < 4; nt++) {
                acc[mt][nt][0] *= f1; acc[mt][nt][1] *= f1;
                acc[mt][nt][2] *= f2; acc[mt][nt][3] *= f2;
            }
        }
        #pragma unroll
        for (int ks = 0; ks < 4; ks++) {
            unsigned af[2][4], bfv[4][2];
            #pragma unroll
            for (int mt = 0; mt < 2; mt++) {
                int rr = wm * 32 + mt * 16 + gid;
                af[mt][0] = S[rr * 36 + ks * 8 + tig];
                af[mt][1] = S[(rr + 8) * 36 + ks * 8 + tig];
                af[mt][2] = S[rr * 36 + ks * 8 + 4 + tig];
                af[mt][3] = S[(rr + 8) * 36 + ks * 8 + 4 + tig];
            }
            #pragma unroll
            for (int nt = 0; nt < 4; nt++) {
                int c = wn * 32 + nt * 8 + gid;
                bfv[nt][0] = Vs[buf][(ks * 8 + tig) * 72 + c];
                bfv[nt][1] = Vs[buf][(ks * 8 + 4 + tig) * 72 + c];
            }
            #pragma unroll
            for (int mt = 0; mt < 2; mt++)
                #pragma unroll
                for (int nt = 0; nt < 4; nt++)
                    mma_f16(acc[mt][nt], af[mt][0], af[mt][1], af[mt][2], af[mt][3],
                            bfv[nt][0], bfv[nt][1]);
        }
    }

    // epilogue: divide by l, write ctx fp16
    #pragma unroll
    for (int mt = 0; mt < 2; mt++) {
        int rr = wm * 32 + mt * 16 + gid;
        float rinv1 = 1.0f / l_s[rr];
        float rinv2 = 1.0f / l_s[rr + 8];
        int rg1 = bi + rr;
        #pragma unroll
        for (int nt = 0; nt < 4; nt++) {
            int c0 = wn * 32 + nt * 8 + 2 * tig;
            *(unsigned*)&ctx16[((size_t)(b * T + rg1) * H + h) * DK + c0] =
                packh2(acc[mt][nt][0] * rinv1, acc[mt][nt][1] * rinv1);
            *(unsigned*)&ctx16[((size_t)(b * T + rg1 + 8) * H + h) * DK + c0] =
                packh2(acc[mt][nt][2] * rinv2, acc[mt][nt][3] * rinv2);
        }
    }
}

// ---------------------------------------------------------------------------
extern "C" void kernel_launch(void* const* d_in, const int* in_sizes, int n_in,
                              void* d_out, int out_size)
{
    const float* query = (const float*)d_in[0];
    const float* key   = (const float*)d_in[1];
    const float* value = (const float*)d_in[2];
    const float* pos   = (const float*)d_in[3];
    const float* Wq = (const float*)d_in[4];
    const float* bq = (const float*)d_in[5];
    const float* Wk = (const float*)d_in[6];
    const float* bk = (const float*)d_in[7];
    const float* Wv = (const float*)d_in[8];
    const float* bv = (const float*)d_in[9];
    const float* Wp = (const float*)d_in[10];
    const float* ub = (const float*)d_in[11];
    const float* vb = (const float*)d_in[12];
    const float* Wo = (const float*)d_in[13];
    const float* bo = (const float*)d_in[14];
    float* out = (float*)d_out;

    __half *x16, *q16, *k16, *v16, *p16, *v16i, *ctx16;
    unsigned* w16;
    __nv_bfloat16 *cs, *ps;
    cudaGetSymbolAddress((void**)&x16,    g_x16);
    cudaGetSymbolAddress((void**)&w16,    g_w16);
    cudaGetSymbolAddress((void**)&q16,    g_q16);
    cudaGetSymbolAddress((void**)&k16,    g_k16);
    cudaGetSymbolAddress((void**)&v16,    g_v16);
    cudaGetSymbolAddress((void**)&p16,    g_p16);
    cudaGetSymbolAddress((void**)&v16i,   g_v16i);
    cudaGetSymbolAddress((void**)&cs,     g_cs);
    cudaGetSymbolAddress((void**)&ps,     g_ps);
    cudaGetSymbolAddress((void**)&ctx16,  g_ctx16);

    const int SMEM_GEMM  = (3 * 128 * 20 + 3 * 16 * 136) * 4;   // 56832 B
    const int SMEM_SCORE = 3 * 128 * QS * 4;                    // 55296 B
    cudaFuncSetAttribute(gemm_h16,
        cudaFuncAttributeMaxDynamicSharedMemorySize, SMEM_GEMM);
    cudaFuncSetAttribute(score_fused_f16,
        cudaFuncAttributeMaxDynamicSharedMemorySize, SMEM_SCORE);

    // one-time conversions
    ActPtrs ap;
    ap.in[0] = query; ap.in[1] = key; ap.in[2] = value; ap.in[3] = pos;
    ap.out[0] = x16 + 0 * (size_t)BT * D;
    ap.out[1] = x16 + 1 * (size_t)BT * D;
    ap.out[2] = x16 + 2 * (size_t)BT * D;
    ap.out[3] = x16 + 3 * (size_t)BT * D;
    cvt_act<<<dim3(BT * D / (8 * 256), 4), 256>>>(ap);

    WPtrs wp;
    wp.in[0] = Wq; wp.in[1] = Wk; wp.in[2] = Wv; wp.in[3] = Wp; wp.in[4] = Wo;
    for (int i = 0; i < 5; i++) wp.out[i] = w16 + (size_t)i * (D * D / 2);
    cvt_w<<<dim3(128, 5), 256>>>(wp);

    // GEMMs
    GArgs ga;
    ga.A[0] = ap.out[0]; ga.A[1] = ap.out[1]; ga.A[2] = ap.out[2]; ga.A[3] = ap.out[3];
    ga.A[4] = ctx16;
    for (int i = 0; i < 5; i++) ga.W[i] = wp.out[i];
    ga.bias[0] = bq; ga.bias[1] = bk; ga.bias[2] = bv; ga.bias[3] = nullptr; ga.bias[4] = bo;
    ga.Ch[0] = q16; ga.Ch[1] = k16; ga.Ch[2] = v16; ga.Ch[3] = p16; ga.Ch[4] = nullptr;
    ga.Cf[0] = ga.Cf[1] = ga.Cf[2] = ga.Cf[3] = nullptr; ga.Cf[4] = out;

    dim3 gproj(D / 128, BT / 128, 4);       // (4, 64, 4)
    gemm_h16<<<gproj, 256, SMEM_GEMM>>>(ga, 0);

    v_reshape<<<1024, 256>>>(v16, v16i);

    dim3 gsc(T / 128, T / 128, B * H);      // (8, 8, 64)
    score_fused_f16<<<gsc, 256, SMEM_SCORE>>>(q16, k16, p16, ub, vb, cs, ps);

    dim3 gfl(T / 128, B * H);               // (8, 64)
    flash_ctx<<<gfl, 256>>>(cs, ps, v16i, ctx16);

    dim3 gout(D / 128, BT / 128, 1);        // (4, 64)
    gemm_h16<<<gout, 256, SMEM_GEMM>>>(ga, 4);
}

// round 12
// speedup vs baseline: 1.5165x; 1.5165x over previous
#include <cuda_runtime.h>
#include <cuda_fp16.h>
#include <cuda_bf16.h>

#define B 8
#define T 1024
#define D 512
#define H 8
#define DK 64
#define BT (B*T)   // 8192

// Scratch (static device globals — no runtime allocation)
__device__ __half g_x16[4][BT * D];          // fp16 copies of query/key/value/pos
__device__ unsigned g_w16[5][D * D / 2];     // k-paired half2 weights
__device__ __half g_q16[BT * D];
__device__ __half g_k16[BT * D];
__device__ __half g_v16[BT * D];
__device__ __half g_p16[BT * D];
__device__ __half g_v16i[BT * D];            // [bh][t/2][d] k-paired half2 words
__device__ __nv_bfloat16 g_cs[(size_t)B * H * T * T];
__device__ __nv_bfloat16 g_ps[(size_t)B * H * T * T];
__device__ __half g_attn16[(size_t)B * H * T * T];
__device__ __half g_ctx16[BT * D];

__device__ __forceinline__ unsigned packh2(float lo, float hi) {
    __half2 h = __floats2half2_rn(lo, hi);
    return *(unsigned*)&h;
}
__device__ __forceinline__ float2 unpackh2(unsigned u) {
    __half2 h = *(__half2*)&u;
    return __half22float2(h);
}

// mma.sync m16n8k16 f16 row.col, fp32 accumulate
__device__ __forceinline__ void mma_f16(float* c, unsigned a0, unsigned a1,
                                        unsigned a2, unsigned a3,
                                        unsigned b0, unsigned b1) {
    asm volatile(
        "mma.sync.aligned.m16n8k16.row.col.f32.f16.f16.f32 "
        "{%0,%1,%2,%3}, {%4,%5,%6,%7}, {%8,%9}, {%0,%1,%2,%3};"
        : "+f"(c[0]), "+f"(c[1]), "+f"(c[2]), "+f"(c[3])
        : "r"(a0), "r"(a1), "r"(a2), "r"(a3), "r"(b0), "r"(b1));
}

__device__ __forceinline__ void cp16g(void* dst, const void* src) {
    unsigned d = (unsigned)__cvta_generic_to_shared(dst);
    asm volatile("cp.async.ca.shared.global [%0], [%1], 16;" :: "r"(d), "l"(src));
}
__device__ __forceinline__ void cp_commit() { asm volatile("cp.async.commit_group;"); }
__device__ __forceinline__ void cp_wait1()  { asm volatile("cp.async.wait_group 1;"); }
__device__ __forceinline__ void cp_wait0()  { asm volatile("cp.async.wait_group 0;"); }

__device__ __forceinline__ float bf2f(unsigned short u) {
    return __uint_as_float(((unsigned)u) << 16);
}

// ---------------------------------------------------------------------------
// One-time conversions
// ---------------------------------------------------------------------------
struct ActPtrs { const float* in[4]; __half* out[4]; };

__global__ __launch_bounds__(256) void cvt_act(ActPtrs ap)
{
    int z = blockIdx.y;
    const float* in = ap.in[z];
    __half* out = ap.out[z];
    size_t i = ((size_t)blockIdx.x * 256 + threadIdx.x) * 8;
    float4 a = *(const float4*)&in[i];
    float4 b = *(const float4*)&in[i + 4];
    uint4 o;
    o.x = packh2(a.x, a.y); o.y = packh2(a.z, a.w);
    o.z = packh2(b.x, b.y); o.w = packh2(b.z, b.w);
    *(uint4*)&out[i] = o;
}

struct WPtrs { const float* in[5]; unsigned* out[5]; };

__global__ __launch_bounds__(256) void cvt_w(WPtrs wp)
{
    int z = blockIdx.y;
    const float* W = wp.in[z];
    unsigned* O = wp.out[z];
    int idx = blockIdx.x * 256 + threadIdx.x;
    int kp = idx >> 7, n4 = (idx & 127) * 4;
    float4 w0 = *(const float4*)&W[(size_t)(2 * kp) * D + n4];
    float4 w1 = *(const float4*)&W[(size_t)(2 * kp + 1) * D + n4];
    uint4 o;
    o.x = packh2(w0.x, w1.x); o.y = packh2(w0.y, w1.y);
    o.z = packh2(w0.z, w1.z); o.w = packh2(w0.w, w1.w);
    *(uint4*)&O[(size_t)kp * D + n4] = o;
}

// ---------------------------------------------------------------------------
// GEMM (all fp16, cp.async 3-stage): C = A[M,512]@W[512,512] + bias.
// Block 128x128, 256 thr (8 warps 2x4), warp 64x32, K-step 32, 1 sync/step.
// ---------------------------------------------------------------------------
struct GArgs {
    const __half* A[5];
    const unsigned* W[5];
    const float* bias[5];
    __half* Ch[5];
    float* Cf[5];
};

__global__ __launch_bounds__(256) void gemm_h16(GArgs ga, int base)
{
    const int N = D, K = D;
    int gi = base + blockIdx.z;
    const __half* A = ga.A[gi];
    const unsigned* W = ga.W[gi];
    const float* bias = ga.bias[gi];
    __half* Ch = ga.Ch[gi];
    float* Cf = ga.Cf[gi];

    extern __shared__ unsigned sm[];
    unsigned* As = sm;
    unsigned* Ws = sm + 3 * 128 * 20;

    int tid = threadIdx.x, warp = tid >> 5, lane = tid & 31;
    int gid = lane >> 2, tig = lane & 3;
    int wm = warp & 1, wn = warp >> 1;
    int bm = blockIdx.y * 128, bn = blockIdx.x * 128;

    const int nsteps = K / 32;

    int arow0 = tid >> 2, ac0 = tid & 3;
    int arow1 = arow0 + 64;
    int wkk0 = tid >> 5, wc0 = tid & 31;
    int wkk1 = wkk0 + 8;

    #pragma unroll
    for (int s = 0; s < 2; s++) {
        int k0 = s * 32;
        unsigned* as = As + (s % 3) * (128 * 20);
        unsigned* ws = Ws + (s % 3) * (16 * 136);
        cp16g(as + arow0 * 20 + ac0 * 4, A + (size_t)(bm + arow0) * K + k0 + ac0 * 8);
        cp16g(as + arow1 * 20 + ac0 * 4, A + (size_t)(bm + arow1) * K + k0 + ac0 * 8);
        cp16g(ws + wkk0 * 136 + wc0 * 4, W + (size_t)(k0 / 2 + wkk0) * N + bn + wc0 * 4);
        cp16g(ws + wkk1 * 136 + wc0 * 4, W + (size_t)(k0 / 2 + wkk1) * N + bn + wc0 * 4);
        cp_commit();
    }

    float acc[4][4][4] = {};
    for (int s = 0; s < nsteps; s++) {
        cp_wait1();
        __syncthreads();
        int st = s % 3;
        if (s + 2 < nsteps) {
            int k0 = (s + 2) * 32, st2 = (s + 2) % 3;
            unsigned* as = As + st2 * (128 * 20);
            unsigned* ws = Ws + st2 * (16 * 136);
            cp16g(as + arow0 * 20 + ac0 * 4, A + (size_t)(bm + arow0) * K + k0 + ac0 * 8);
            cp16g(as + arow1 * 20 + ac0 * 4, A + (size_t)(bm + arow1) * K + k0 + ac0 * 8);
            cp16g(ws + wkk0 * 136 + wc0 * 4, W + (size_t)(k0 / 2 + wkk0) * N + bn + wc0 * 4);
            cp16g(ws + wkk1 * 136 + wc0 * 4, W + (size_t)(k0 / 2 + wkk1) * N + bn + wc0 * 4);
        }
        cp_commit();

        const unsigned* as = As + st * (128 * 20);
        const unsigned* ws = Ws + st * (16 * 136);
        #pragma unroll
        for (int ks = 0; ks < 2; ks++) {
            unsigned af[4][4], bf[4][2];
            #pragma unroll
            for (int mt = 0; mt < 4; mt++) {
                int r = wm * 64 + mt * 16 + gid;
                af[mt][0] = as[r * 20 + ks * 8 + tig];
                af[mt][1] = as[(r + 8) * 20 + ks * 8 + tig];
                af[mt][2] = as[r * 20 + ks * 8 + 4 + tig];
                af[mt][3] = as[(r + 8) * 20 + ks * 8 + 4 + tig];
            }
            #pragma unroll
            for (int nt = 0; nt < 4; nt++) {
                int c = wn * 32 + nt * 8 + gid;
                bf[nt][0] = ws[(ks * 8 + tig) * 136 + c];
                bf[nt][1] = ws[(ks * 8 + 4 + tig) * 136 + c];
            }
            #pragma unroll
            for (int mt = 0; mt < 4; mt++)
                #pragma unroll
                for (int nt = 0; nt < 4; nt++)
                    mma_f16(acc[mt][nt], af[mt][0], af[mt][1], af[mt][2], af[mt][3],
                            bf[nt][0], bf[nt][1]);
        }
    }

    #pragma unroll
    for (int mt = 0; mt < 4; mt++) {
        int r0 = bm + wm * 64 + mt * 16 + gid;
        #pragma unroll
        for (int nt = 0; nt < 4; nt++) {
            int c0 = bn + wn * 32 + nt * 8 + 2 * tig;
            float b0 = bias ? bias[c0] : 0.f;
            float b1 = bias ? bias[c0 + 1] : 0.f;
            float v0 = acc[mt][nt][0] + b0, v1 = acc[mt][nt][1] + b1;
            float v2 = acc[mt][nt][2] + b0, v3 = acc[mt][nt][3] + b1;
            if (Ch) {
                *(unsigned*)&Ch[(size_t)r0 * N + c0]       = packh2(v0, v1);
                *(unsigned*)&Ch[(size_t)(r0 + 8) * N + c0] = packh2(v2, v3);
            } else {
                Cf[(size_t)r0 * N + c0]           = v0;
                Cf[(size_t)r0 * N + c0 + 1]       = v1;
                Cf[(size_t)(r0 + 8) * N + c0]     = v2;
                Cf[(size_t)(r0 + 8) * N + c0 + 1] = v3;
            }
        }
    }
}

// ---------------------------------------------------------------------------
// V reshuffle: v16 [b][t][h][d] -> v16i [bh][t/2][d] k-paired half2 words.
// ---------------------------------------------------------------------------
__global__ __launch_bounds__(256) void v_reshape(
    const __half* __restrict__ v16, __half* __restrict__ v16i)
{
    int gidx = blockIdx.x * 256 + threadIdx.x;
    int d8 = gidx & 7;
    int rem = gidx >> 3;
    int kk = rem & 511;
    int bh = rem >> 9;
    int b = bh >> 3, h = bh & 7;

    uint4 x = *(const uint4*)(v16 + ((size_t)(b * T + 2 * kk) * H + h) * DK + d8 * 8);
    uint4 y = *(const uint4*)(v16 + ((size_t)(b * T + 2 * kk + 1) * H + h) * DK + d8 * 8);
    const unsigned short* xs = (const unsigned short*)&x;
    const unsigned short* ys = (const unsigned short*)&y;
    unsigned out[8];
    #pragma unroll
    for (int i = 0; i < 8; i++)
        out[i] = (unsigned)xs[i] | ((unsigned)ys[i] << 16);
    unsigned* dst = (unsigned*)v16i + ((size_t)bh * 512 + kk) * 64 + d8 * 8;
    *(uint4*)(dst + 0) = *(uint4*)(out + 0);
    *(uint4*)(dst + 4) = *(uint4*)(out + 4);
}

// ---------------------------------------------------------------------------
// Fused scores (fp16): cs = scale*(q+u)·k, ps = scale*(q+v)·p -> bf16.
// ---------------------------------------------------------------------------
#define QS 36
__device__ __forceinline__ void score_mma_bf16(
    const unsigned* __restrict__ Q, const unsigned* __restrict__ KP,
    __nv_bfloat16* __restrict__ out, size_t obase, int bi, int bj,
    int wm, int wn, int gid, int tig)
{
    float acc[4][4][4] = {};
    #pragma unroll
    for (int ks = 0; ks < 4; ks++) {
        unsigned af[4][4], bf[4][2];
        #pragma unroll
        for (int mt = 0; mt < 4; mt++) {
            int r = wm * 64 + mt * 16 + gid;
            af[mt][0] = Q[r * QS + ks * 8 + tig];
            af[mt][1] = Q[(r + 8) * QS + ks * 8 + tig];
            af[mt][2] = Q[r * QS + ks * 8 + 4 + tig];
            af[mt][3] = Q[(r + 8) * QS + ks * 8 + 4 + tig];
        }
        #pragma unroll
        for (int nt = 0; nt < 4; nt++) {
            int c = wn * 32 + nt * 8 + gid;
            bf[nt][0] = KP[c * QS + ks * 8 + tig];
            bf[nt][1] = KP[c * QS + ks * 8 + 4 + tig];
        }
        #pragma unroll
        for (int mt = 0; mt < 4; mt++)
            #pragma unroll
            for (int nt = 0; nt < 4; nt++)
                mma_f16(acc[mt][nt], af[mt][0], af[mt][1], af[mt][2], af[mt][3],
                        bf[nt][0], bf[nt][1]);
    }
    const float scale = 0.04419417382415922f;   // 1/sqrt(512)
    #pragma unroll
    for (int mt = 0; mt < 4; mt++) {
        int r0 = bi + wm * 64 + mt * 16 + gid;
        #pragma unroll
        for (int nt = 0; nt < 4; nt++) {
            int c0 = bj + wn * 32 + nt * 8 + 2 * tig;
            __nv_bfloat162 p0 = __floats2bfloat162_rn(acc[mt][nt][0] * scale,
                                                      acc[mt][nt][1] * scale);
            __nv_bfloat162 p1 = __floats2bfloat162_rn(acc[mt][nt][2] * scale,
                                                      acc[mt][nt][3] * scale);
            *(__nv_bfloat162*)&out[obase + (size_t)r0 * T + c0]       = p0;
            *(__nv_bfloat162*)&out[obase + (size_t)(r0 + 8) * T + c0] = p1;
        }
    }
}

__global__ __launch_bounds__(256) void score_fused_f16(
    const __half* __restrict__ q16, const __half* __restrict__ k16,
    const __half* __restrict__ p16, const float* __restrict__ ub,
    const float* __restrict__ vb,
    __nv_bfloat16* __restrict__ cs, __nv_bfloat16* __restrict__ ps)
{
    extern __shared__ unsigned smu[];
    unsigned* Qu = smu;
    unsigned* Qv = smu + 128 * QS;
    unsigned* KP = smu + 2 * 128 * QS;
    __shared__ float sub[DK], svb[DK];

    int bh = blockIdx.z, b = bh >> 3, h = bh & 7;
    int bi = blockIdx.y * 128, bj = blockIdx.x * 128;
    int tid = threadIdx.x, warp = tid >> 5, lane = tid & 31;
    int gid = lane >> 2, tig = lane & 3;
    int wm = warp & 1, wn = warp >> 1;
    size_t obase = (size_t)bh * T * T;

    if (tid < DK) {
        sub[tid] = ub[h * DK + tid];
        svb[tid] = vb[h * DK + tid];
    }

    #pragma unroll
    for (int l = 0; l < 4; l++) {
        int idx = tid + l * 256;
        int row = idx >> 3, c16 = idx & 7;
        cp16g((char*)KP + row * (QS * 4) + c16 * 16,
              k16 + ((size_t)(b * T + bj + row) * H + h) * DK + c16 * 8);
    }
    cp_commit();
    __syncthreads();

    {
        int row = tid >> 1, doff = (tid & 1) * 32;
        const uint4* qp = (const uint4*)(q16 + ((size_t)(b * T + bi + row) * H + h) * DK + doff);
        uint4 r4[4] = { qp[0], qp[1], qp[2], qp[3] };
        const unsigned* rw = (const unsigned*)r4;
        unsigned* qud = &Qu[row * QS + doff / 2];
        unsigned* qvd = &Qv[row * QS + doff / 2];
        #pragma unroll
        for (int u = 0; u < 16; u++) {
            float2 f = unpackh2(rw[u]);
            int d = doff + 2 * u;
            qud[u] = packh2(f.x + sub[d], f.y + sub[d + 1]);
            qvd[u] = packh2(f.x + svb[d], f.y + svb[d + 1]);
        }
    }
    cp_wait0();
    __syncthreads();

    score_mma_bf16(Qu, KP, cs, obase, bi, bj, wm, wn, gid, tig);
    __syncthreads();

    #pragma unroll
    for (int l = 0; l < 4; l++) {
        int idx = tid + l * 256;
        int row = idx >> 3, c16 = idx & 7;
        cp16g((char*)KP + row * (QS * 4) + c16 * 16,
              p16 + ((size_t)(b * T + bj + row) * H + h) * DK + c16 * 8);
    }
    cp_commit();
    cp_wait0();
    __syncthreads();

    score_mma_bf16(Qv, KP, ps, obase, bi, bj, wm, wn, gid, tig);
}

// ---------------------------------------------------------------------------
// Warp-per-row fused rel-shift + softmax. 8 rows per block, no block syncs.
//   shifted[i,j] = (j<=i) ? ps[i, T+j-i-1] : (j==i+1) ? 0 : ps[i+1, j-i-2]
// Thread owns 16 pairs (j0 = u*64 + lane*2); pure shfl reductions.
// ---------------------------------------------------------------------------
__global__ __launch_bounds__(256) void softmax_shift_warp(
    const __nv_bfloat16* __restrict__ cs, const __nv_bfloat16* __restrict__ ps,
    __half* __restrict__ attn)
{
    int warp = threadIdx.x >> 5, lane = threadIdx.x & 31;
    int i  = blockIdx.x * 8 + warp;
    int bh = blockIdx.y;
    size_t base = (size_t)bh * T * T;
    const unsigned short* psr = (const unsigned short*)(ps + base);

    float vals[32];
    float mx = -3.4e38f;
    #pragma unroll
    for (int u = 0; u < 16; u++) {
        int j0 = u * 64 + lane * 2;
        unsigned cw = *(const unsigned*)&cs[base + (size_t)i * T + j0];
        #pragma unroll
        for (int e = 0; e < 2; e++) {
            int j = j0 + e;
            float pv;
            if (j <= i)
                pv = bf2f(psr[(size_t)i * T + (T + j - i - 1)]);
            else if (j == i + 1)
                pv = 0.0f;
            else
                pv = bf2f(psr[(size_t)(i + 1) * T + (j - i - 2)]);
            float s = bf2f((unsigned short)(e ? (cw >> 16) : (cw & 0xffff))) + pv;
            vals[2 * u + e] = s;
            mx = fmaxf(mx, s);
        }
    }
    #pragma unroll
    for (int o = 16; o > 0; o >>= 1)
        mx = fmaxf(mx, __shfl_xor_sync(0xffffffffu, mx, o));

    float sum = 0.f;
    #pragma unroll
    for (int u = 0; u < 32; u++) {
        vals[u] = __expf(vals[u] - mx);
        sum += vals[u];
    }
    #pragma unroll
    for (int o = 16; o > 0; o >>= 1)
        sum += __shfl_xor_sync(0xffffffffu, sum, o);
    float rinv = 1.0f / sum;

    #pragma unroll
    for (int u = 0; u < 16; u++) {
        int j0 = u * 64 + lane * 2;
        *(unsigned*)&attn[base + (size_t)i * T + j0] =
            packh2(vals[2 * u] * rinv, vals[2 * u + 1] * rinv);
    }
}

// ---------------------------------------------------------------------------
// Context (fp16): ctx16 = attn @ v. Block 128x64, 8 warps 4x2, K-step 32, 3-stage.
// ---------------------------------------------------------------------------
__global__ __launch_bounds__(256, 2) void context_f16(
    const __half* __restrict__ attn, const __half* __restrict__ v16i,
    __half* __restrict__ ctx16)
{
    __shared__ unsigned As[3][128 * 20];
    __shared__ unsigned Vs[3][16 * 72];
    int bh = blockIdx.y, b = bh >> 3, h = bh & 7;
    int bm = blockIdx.x * 128;
    int tid = threadIdx.x, warp = tid >> 5, lane = tid & 31;
    int gid = lane >> 2, tig = lane & 3;
    int wm = warp >> 1, wn = warp & 1;
    size_t abase = (size_t)bh * T * T;
    const unsigned* vsrc = (const unsigned*)v16i + (size_t)bh * 512 * 64;

    const int nsteps = T / 32;

    #pragma unroll
    for (int s = 0; s < 2; s++) {
        int k0 = s * 32;
        #pragma unroll
        for (int l = 0; l < 2; l++) {
            int idx = tid + l * 256;
            int row = idx >> 2, c = idx & 3;
            cp16g((char*)As[s] + row * 80 + c * 16,
                  attn + abase + (size_t)(bm + row) * T + k0 + c * 8);
        }
        {
            int kk = tid >> 4, c = tid & 15;
            cp16g((char*)Vs[s] + kk * 288 + c * 16,
                  vsrc + (size_t)(k0 / 2 + kk) * 64 + c * 4);
        }
        cp_commit();
    }

    float acc[2][4][4] = {};
    for (int s = 0; s < nsteps; s++) {
        cp_wait1();
        __syncthreads();
        int st = s % 3;
        if (s + 2 < nsteps) {
            int k0 = (s + 2) * 32, st2 = (s + 2) % 3;
            #pragma unroll
            for (int l = 0; l < 2; l++) {
                int idx = tid + l * 256;
                int row = idx >> 2, c = idx & 3;
                cp16g((char*)As[st2] + row * 80 + c * 16,
                      attn + abase + (size_t)(bm + row) * T + k0 + c * 8);
            }
            int kk = tid >> 4, c = tid & 15;
            cp16g((char*)Vs[st2] + kk * 288 + c * 16,
                  vsrc + (size_t)(k0 / 2 + kk) * 64 + c * 4);
        }
        cp_commit();

        #pragma unroll
        for (int ks = 0; ks < 2; ks++) {
            unsigned af[2][4], bf[4][2];
            #pragma unroll
            for (int mt = 0; mt < 2; mt++) {
                int r = wm * 32 + mt * 16 + gid;
                af[mt][0] = As[st][r * 20 + ks * 8 + tig];
                af[mt][1] = As[st][(r + 8) * 20 + ks * 8 + tig];
                af[mt][2] = As[st][r * 20 + ks * 8 + 4 + tig];
                af[mt][3] = As[st][(r + 8) * 20 + ks * 8 + 4 + tig];
            }
            #pragma unroll
            for (int nt = 0; nt < 4; nt++) {
                int c = wn * 32 + nt * 8 + gid;
                bf[nt][0] = Vs[st][(ks * 8 + tig) * 72 + c];
                bf[nt][1] = Vs[st][(ks * 8 + 4 + tig) * 72 + c];
            }
            #pragma unroll
            for (int mt = 0; mt < 2; mt++)
                #pragma unroll
                for (int nt = 0; nt < 4; nt++)
                    mma_f16(acc[mt][nt], af[mt][0], af[mt][1], af[mt][2], af[mt][3],
                            bf[nt][0], bf[nt][1]);
        }
    }

    #pragma unroll
    for (int mt = 0; mt < 2; mt++) {
        int r0 = bm + wm * 32 + mt * 16 + gid;
        #pragma unroll
        for (int nt = 0; nt < 4; nt++) {
            int c0 = wn * 32 + nt * 8 + 2 * tig;
            *(unsigned*)&ctx16[((size_t)(b * T + r0) * H + h) * DK + c0] =
                packh2(acc[mt][nt][0], acc[mt][nt][1]);
            *(unsigned*)&ctx16[((size_t)(b * T + r0 + 8) * H + h) * DK + c0] =
                packh2(acc[mt][nt][2], acc[mt][nt][3]);
        }
    }
}

// ---------------------------------------------------------------------------
extern "C" void kernel_launch(void* const* d_in, const int* in_sizes, int n_in,
                              void* d_out, int out_size)
{
    const float* query = (const float*)d_in[0];
    const float* key   = (const float*)d_in[1];
    const float* value = (const float*)d_in[2];
    const float* pos   = (const float*)d_in[3];
    const float* Wq = (const float*)d_in[4];
    const float* bq = (const float*)d_in[5];
    const float* Wk = (const float*)d_in[6];
    const float* bk = (const float*)d_in[7];
    const float* Wv = (const float*)d_in[8];
    const float* bv = (const float*)d_in[9];
    const float* Wp = (const float*)d_in[10];
    const float* ub = (const float*)d_in[11];
    const float* vb = (const float*)d_in[12];
    const float* Wo = (const float*)d_in[13];
    const float* bo = (const float*)d_in[14];
    float* out = (float*)d_out;

    __half *x16, *q16, *k16, *v16, *p16, *v16i, *attn16, *ctx16;
    unsigned* w16;
    __nv_bfloat16 *cs, *ps;
    cudaGetSymbolAddress((void**)&x16,    g_x16);
    cudaGetSymbolAddress((void**)&w16,    g_w16);
    cudaGetSymbolAddress((void**)&q16,    g_q16);
    cudaGetSymbolAddress((void**)&k16,    g_k16);
    cudaGetSymbolAddress((void**)&v16,    g_v16);
    cudaGetSymbolAddress((void**)&p16,    g_p16);
    cudaGetSymbolAddress((void**)&v16i,   g_v16i);
    cudaGetSymbolAddress((void**)&cs,     g_cs);
    cudaGetSymbolAddress((void**)&ps,     g_ps);
    cudaGetSymbolAddress((void**)&attn16, g_attn16);
    cudaGetSymbolAddress((void**)&ctx16,  g_ctx16);

    const int SMEM_GEMM  = (3 * 128 * 20 + 3 * 16 * 136) * 4;   // 56832 B
    const int SMEM_SCORE = 3 * 128 * QS * 4;                    // 55296 B
    cudaFuncSetAttribute(gemm_h16,
        cudaFuncAttributeMaxDynamicSharedMemorySize, SMEM_GEMM);
    cudaFuncSetAttribute(score_fused_f16,
        cudaFuncAttributeMaxDynamicSharedMemorySize, SMEM_SCORE);

    // one-time conversions
    ActPtrs ap;
    ap.in[0] = query; ap.in[1] = key; ap.in[2] = value; ap.in[3] = pos;
    ap.out[0] = x16 + 0 * (size_t)BT * D;
    ap.out[1] = x16 + 1 * (size_t)BT * D;
    ap.out[2] = x16 + 2 * (size_t)BT * D;
    ap.out[3] = x16 + 3 * (size_t)BT * D;
    cvt_act<<<dim3(BT * D / (8 * 256), 4), 256>>>(ap);

    WPtrs wp;
    wp.in[0] = Wq; wp.in[1] = Wk; wp.in[2] = Wv; wp.in[3] = Wp; wp.in[4] = Wo;
    for (int i = 0; i < 5; i++) wp.out[i] = w16 + (size_t)i * (D * D / 2);
    cvt_w<<<dim3(128, 5), 256>>>(wp);

    // GEMMs
    GArgs ga;
    ga.A[0] = ap.out[0]; ga.A[1] = ap.out[1]; ga.A[2] = ap.out[2]; ga.A[3] = ap.out[3];
    ga.A[4] = ctx16;
    for (int i = 0; i < 5; i++) ga.W[i] = wp.out[i];
    ga.bias[0] = bq; ga.bias[1] = bk; ga.bias[2] = bv; ga.bias[3] = nullptr; ga.bias[4] = bo;
    ga.Ch[0] = q16; ga.Ch[1] = k16; ga.Ch[2] = v16; ga.Ch[3] = p16; ga.Ch[4] = nullptr;
    ga.Cf[0] = ga.Cf[1] = ga.Cf[2] = ga.Cf[3] = nullptr; ga.Cf[4] = out;

    dim3 gproj(D / 128, BT / 128, 4);       // (4, 64, 4)
    gemm_h16<<<gproj, 256, SMEM_GEMM>>>(ga, 0);

    v_reshape<<<1024, 256>>>(v16, v16i);

    dim3 gsc(T / 128, T / 128, B * H);      // (8, 8, 64)
    score_fused_f16<<<gsc, 256, SMEM_SCORE>>>(q16, k16, p16, ub, vb, cs, ps);

    dim3 gsm(T / 8, B * H);                 // (128, 64)
    softmax_shift_warp<<<gsm, 256>>>(cs, ps, attn16);

    dim3 gctx(T / 128, B * H);              // (8, 64)
    context_f16<<<gctx, 256>>>(attn16, v16i, ctx16);

    dim3 gout(D / 128, BT / 128, 1);        // (4, 64)
    gemm_h16<<<gout, 256, SMEM_GEMM>>>(ga, 4);
}

// round 13
// speedup vs baseline: 1.7062x; 1.1251x over previous
#include <cuda_runtime.h>
#include <cuda_fp16.h>
#include <cuda_bf16.h>

#define B 8
#define T 1024
#define D 512
#define H 8
#define DK 64
#define BT (B*T)   // 8192

// Scratch (static device globals — no runtime allocation)
__device__ __half g_x16[4][BT * D];          // fp16 copies of query/key/value/pos
__device__ unsigned g_w16[5][D * D / 2];     // k-paired half2 weights
__device__ __half g_q16[BT * D];
__device__ __half g_k16[BT * D];
__device__ __half g_v16[BT * D];
__device__ __half g_p16[BT * D];
__device__ __half g_v16i[BT * D];            // [bh][t/2][d] k-paired half2 words
__device__ __nv_bfloat16 g_cs[(size_t)B * H * T * T];
__device__ __nv_bfloat16 g_ps[(size_t)B * H * T * T];
__device__ __half g_attn16[(size_t)B * H * T * T];
__device__ __half g_ctx16[BT * D];

__device__ __forceinline__ unsigned packh2(float lo, float hi) {
    __half2 h = __floats2half2_rn(lo, hi);
    return *(unsigned*)&h;
}
__device__ __forceinline__ float2 unpackh2(unsigned u) {
    __half2 h = *(__half2*)&u;
    return __half22float2(h);
}

// mma.sync m16n8k16 f16 row.col, fp32 accumulate
__device__ __forceinline__ void mma_f16(float* c, unsigned a0, unsigned a1,
                                        unsigned a2, unsigned a3,
                                        unsigned b0, unsigned b1) {
    asm volatile(
        "mma.sync.aligned.m16n8k16.row.col.f32.f16.f16.f32 "
        "{%0,%1,%2,%3}, {%4,%5,%6,%7}, {%8,%9}, {%0,%1,%2,%3};"
        : "+f"(c[0]), "+f"(c[1]), "+f"(c[2]), "+f"(c[3])
        : "r"(a0), "r"(a1), "r"(a2), "r"(a3), "r"(b0), "r"(b1));
}

__device__ __forceinline__ void cp16g(void* dst, const void* src) {
    unsigned d = (unsigned)__cvta_generic_to_shared(dst);
    asm volatile("cp.async.ca.shared.global [%0], [%1], 16;" :: "r"(d), "l"(src));
}
__device__ __forceinline__ void cp_commit() { asm volatile("cp.async.commit_group;"); }
__device__ __forceinline__ void cp_wait1()  { asm volatile("cp.async.wait_group 1;"); }
__device__ __forceinline__ void cp_wait0()  { asm volatile("cp.async.wait_group 0;"); }

__device__ __forceinline__ float bf2f(unsigned short u) {
    return __uint_as_float(((unsigned)u) << 16);
}

// ---------------------------------------------------------------------------
// One-time conversions
// ---------------------------------------------------------------------------
struct ActPtrs { const float* in[4]; __half* out[4]; };

__global__ __launch_bounds__(256) void cvt_act(ActPtrs ap)
{
    int z = blockIdx.y;
    const float* in = ap.in[z];
    __half* out = ap.out[z];
    size_t i = ((size_t)blockIdx.x * 256 + threadIdx.x) * 8;
    float4 a = *(const float4*)&in[i];
    float4 b = *(const float4*)&in[i + 4];
    uint4 o;
    o.x = packh2(a.x, a.y); o.y = packh2(a.z, a.w);
    o.z = packh2(b.x, b.y); o.w = packh2(b.z, b.w);
    *(uint4*)&out[i] = o;
}

struct WPtrs { const float* in[5]; unsigned* out[5]; };

__global__ __launch_bounds__(256) void cvt_w(WPtrs wp)
{
    int z = blockIdx.y;
    const float* W = wp.in[z];
    unsigned* O = wp.out[z];
    int idx = blockIdx.x * 256 + threadIdx.x;
    int kp = idx >> 7, n4 = (idx & 127) * 4;
    float4 w0 = *(const float4*)&W[(size_t)(2 * kp) * D + n4];
    float4 w1 = *(const float4*)&W[(size_t)(2 * kp + 1) * D + n4];
    uint4 o;
    o.x = packh2(w0.x, w1.x); o.y = packh2(w0.y, w1.y);
    o.z = packh2(w0.z, w1.z); o.w = packh2(w0.w, w1.w);
    *(uint4*)&O[(size_t)kp * D + n4] = o;
}

// ---------------------------------------------------------------------------
// GEMM (all fp16, cp.async 3-stage): C = A[M,512]@W[512,512] + bias.
// Block 128x128, 256 thr (8 warps 2x4), warp 64x32, K-step 32, 1 sync/step.
// ---------------------------------------------------------------------------
struct GArgs {
    const __half* A[5];
    const unsigned* W[5];
    const float* bias[5];
    __half* Ch[5];
    float* Cf[5];
};

__global__ __launch_bounds__(256) void gemm_h16(GArgs ga, int base)
{
    const int N = D, K = D;
    int gi = base + blockIdx.z;
    const __half* A = ga.A[gi];
    const unsigned* W = ga.W[gi];
    const float* bias = ga.bias[gi];
    __half* Ch = ga.Ch[gi];
    float* Cf = ga.Cf[gi];

    extern __shared__ unsigned sm[];
    unsigned* As = sm;
    unsigned* Ws = sm + 3 * 128 * 20;

    int tid = threadIdx.x, warp = tid >> 5, lane = tid & 31;
    int gid = lane >> 2, tig = lane & 3;
    int wm = warp & 1, wn = warp >> 1;
    int bm = blockIdx.y * 128, bn = blockIdx.x * 128;

    const int nsteps = K / 32;

    int arow0 = tid >> 2, ac0 = tid & 3;
    int arow1 = arow0 + 64;
    int wkk0 = tid >> 5, wc0 = tid & 31;
    int wkk1 = wkk0 + 8;

    #pragma unroll
    for (int s = 0; s < 2; s++) {
        int k0 = s * 32;
        unsigned* as = As + (s % 3) * (128 * 20);
        unsigned* ws = Ws + (s % 3) * (16 * 136);
        cp16g(as + arow0 * 20 + ac0 * 4, A + (size_t)(bm + arow0) * K + k0 + ac0 * 8);
        cp16g(as + arow1 * 20 + ac0 * 4, A + (size_t)(bm + arow1) * K + k0 + ac0 * 8);
        cp16g(ws + wkk0 * 136 + wc0 * 4, W + (size_t)(k0 / 2 + wkk0) * N + bn + wc0 * 4);
        cp16g(ws + wkk1 * 136 + wc0 * 4, W + (size_t)(k0 / 2 + wkk1) * N + bn + wc0 * 4);
        cp_commit();
    }

    float acc[4][4][4] = {};
    for (int s = 0; s < nsteps; s++) {
        cp_wait1();
        __syncthreads();
        int st = s % 3;
        if (s + 2 < nsteps) {
            int k0 = (s + 2) * 32, st2 = (s + 2) % 3;
            unsigned* as = As + st2 * (128 * 20);
            unsigned* ws = Ws + st2 * (16 * 136);
            cp16g(as + arow0 * 20 + ac0 * 4, A + (size_t)(bm + arow0) * K + k0 + ac0 * 8);
            cp16g(as + arow1 * 20 + ac0 * 4, A + (size_t)(bm + arow1) * K + k0 + ac0 * 8);
            cp16g(ws + wkk0 * 136 + wc0 * 4, W + (size_t)(k0 / 2 + wkk0) * N + bn + wc0 * 4);
            cp16g(ws + wkk1 * 136 + wc0 * 4, W + (size_t)(k0 / 2 + wkk1) * N + bn + wc0 * 4);
        }
        cp_commit();

        const unsigned* as = As + st * (128 * 20);
        const unsigned* ws = Ws + st * (16 * 136);
        #pragma unroll
        for (int ks = 0; ks < 2; ks++) {
            unsigned af[4][4], bf[4][2];
            #pragma unroll
            for (int mt = 0; mt < 4; mt++) {
                int r = wm * 64 + mt * 16 + gid;
                af[mt][0] = as[r * 20 + ks * 8 + tig];
                af[mt][1] = as[(r + 8) * 20 + ks * 8 + tig];
                af[mt][2] = as[r * 20 + ks * 8 + 4 + tig];
                af[mt][3] = as[(r + 8) * 20 + ks * 8 + 4 + tig];
            }
            #pragma unroll
            for (int nt = 0; nt < 4; nt++) {
                int c = wn * 32 + nt * 8 + gid;
                bf[nt][0] = ws[(ks * 8 + tig) * 136 + c];
                bf[nt][1] = ws[(ks * 8 + 4 + tig) * 136 + c];
            }
            #pragma unroll
            for (int mt = 0; mt < 4; mt++)
                #pragma unroll
                for (int nt = 0; nt < 4; nt++)
                    mma_f16(acc[mt][nt], af[mt][0], af[mt][1], af[mt][2], af[mt][3],
                            bf[nt][0], bf[nt][1]);
        }
    }

    #pragma unroll
    for (int mt = 0; mt < 4; mt++) {
        int r0 = bm + wm * 64 + mt * 16 + gid;
        #pragma unroll
        for (int nt = 0; nt < 4; nt++) {
            int c0 = bn + wn * 32 + nt * 8 + 2 * tig;
            float b0 = bias ? bias[c0] : 0.f;
            float b1 = bias ? bias[c0 + 1] : 0.f;
            float v0 = acc[mt][nt][0] + b0, v1 = acc[mt][nt][1] + b1;
            float v2 = acc[mt][nt][2] + b0, v3 = acc[mt][nt][3] + b1;
            if (Ch) {
                *(unsigned*)&Ch[(size_t)r0 * N + c0]       = packh2(v0, v1);
                *(unsigned*)&Ch[(size_t)(r0 + 8) * N + c0] = packh2(v2, v3);
            } else {
                Cf[(size_t)r0 * N + c0]           = v0;
                Cf[(size_t)r0 * N + c0 + 1]       = v1;
                Cf[(size_t)(r0 + 8) * N + c0]     = v2;
                Cf[(size_t)(r0 + 8) * N + c0 + 1] = v3;
            }
        }
    }
}

// ---------------------------------------------------------------------------
// V reshuffle: v16 [b][t][h][d] -> v16i [bh][t/2][d] k-paired half2 words.
// ---------------------------------------------------------------------------
__global__ __launch_bounds__(256) void v_reshape(
    const __half* __restrict__ v16, __half* __restrict__ v16i)
{
    int gidx = blockIdx.x * 256 + threadIdx.x;
    int d8 = gidx & 7;
    int rem = gidx >> 3;
    int kk = rem & 511;
    int bh = rem >> 9;
    int b = bh >> 3, h = bh & 7;

    uint4 x = *(const uint4*)(v16 + ((size_t)(b * T + 2 * kk) * H + h) * DK + d8 * 8);
    uint4 y = *(const uint4*)(v16 + ((size_t)(b * T + 2 * kk + 1) * H + h) * DK + d8 * 8);
    const unsigned short* xs = (const unsigned short*)&x;
    const unsigned short* ys = (const unsigned short*)&y;
    unsigned out[8];
    #pragma unroll
    for (int i = 0; i < 8; i++)
        out[i] = (unsigned)xs[i] | ((unsigned)ys[i] << 16);
    unsigned* dst = (unsigned*)v16i + ((size_t)bh * 512 + kk) * 64 + d8 * 8;
    *(uint4*)(dst + 0) = *(uint4*)(out + 0);
    *(uint4*)(dst + 4) = *(uint4*)(out + 4);
}

// ---------------------------------------------------------------------------
// Fused scores (fp16): cs = scale*(q+u)·k, ps = scale*(q+v)·p -> bf16.
// ---------------------------------------------------------------------------
#define QS 36
__device__ __forceinline__ void score_mma_bf16(
    const unsigned* __restrict__ Q, const unsigned* __restrict__ KP,
    __nv_bfloat16* __restrict__ out, size_t obase, int bi, int bj,
    int wm, int wn, int gid, int tig)
{
    float acc[4][4][4] = {};
    #pragma unroll
    for (int ks = 0; ks < 4; ks++) {
        unsigned af[4][4], bf[4][2];
        #pragma unroll
        for (int mt = 0; mt < 4; mt++) {
            int r = wm * 64 + mt * 16 + gid;
            af[mt][0] = Q[r * QS + ks * 8 + tig];
            af[mt][1] = Q[(r + 8) * QS + ks * 8 + tig];
            af[mt][2] = Q[r * QS + ks * 8 + 4 + tig];
            af[mt][3] = Q[(r + 8) * QS + ks * 8 + 4 + tig];
        }
        #pragma unroll
        for (int nt = 0; nt < 4; nt++) {
            int c = wn * 32 + nt * 8 + gid;
            bf[nt][0] = KP[c * QS + ks * 8 + tig];
            bf[nt][1] = KP[c * QS + ks * 8 + 4 + tig];
        }
        #pragma unroll
        for (int mt = 0; mt < 4; mt++)
            #pragma unroll
            for (int nt = 0; nt < 4; nt++)
                mma_f16(acc[mt][nt], af[mt][0], af[mt][1], af[mt][2], af[mt][3],
                        bf[nt][0], bf[nt][1]);
    }
    const float scale = 0.04419417382415922f;   // 1/sqrt(512)
    #pragma unroll
    for (int mt = 0; mt < 4; mt++) {
        int r0 = bi + wm * 64 + mt * 16 + gid;
        #pragma unroll
        for (int nt = 0; nt < 4; nt++) {
            int c0 = bj + wn * 32 + nt * 8 + 2 * tig;
            __nv_bfloat162 p0 = __floats2bfloat162_rn(acc[mt][nt][0] * scale,
                                                      acc[mt][nt][1] * scale);
            __nv_bfloat162 p1 = __floats2bfloat162_rn(acc[mt][nt][2] * scale,
                                                      acc[mt][nt][3] * scale);
            *(__nv_bfloat162*)&out[obase + (size_t)r0 * T + c0]       = p0;
            *(__nv_bfloat162*)&out[obase + (size_t)(r0 + 8) * T + c0] = p1;
        }
    }
}

__global__ __launch_bounds__(256) void score_fused_f16(
    const __half* __restrict__ q16, const __half* __restrict__ k16,
    const __half* __restrict__ p16, const float* __restrict__ ub,
    const float* __restrict__ vb,
    __nv_bfloat16* __restrict__ cs, __nv_bfloat16* __restrict__ ps)
{
    extern __shared__ unsigned smu[];
    unsigned* Qu = smu;
    unsigned* Qv = smu + 128 * QS;
    unsigned* KP = smu + 2 * 128 * QS;
    __shared__ float sub[DK], svb[DK];

    int bh = blockIdx.z, b = bh >> 3, h = bh & 7;
    int bi = blockIdx.y * 128, bj = blockIdx.x * 128;
    int tid = threadIdx.x, warp = tid >> 5, lane = tid & 31;
    int gid = lane >> 2, tig = lane & 3;
    int wm = warp & 1, wn = warp >> 1;
    size_t obase = (size_t)bh * T * T;

    if (tid < DK) {
        sub[tid] = ub[h * DK + tid];
        svb[tid] = vb[h * DK + tid];
    }

    #pragma unroll
    for (int l = 0; l < 4; l++) {
        int idx = tid + l * 256;
        int row = idx >> 3, c16 = idx & 7;
        cp16g((char*)KP + row * (QS * 4) + c16 * 16,
              k16 + ((size_t)(b * T + bj + row) * H + h) * DK + c16 * 8);
    }
    cp_commit();
    __syncthreads();

    {
        int row = tid >> 1, doff = (tid & 1) * 32;
        const uint4* qp = (const uint4*)(q16 + ((size_t)(b * T + bi + row) * H + h) * DK + doff);
        uint4 r4[4] = { qp[0], qp[1], qp[2], qp[3] };
        const unsigned* rw = (const unsigned*)r4;
        unsigned* qud = &Qu[row * QS + doff / 2];
        unsigned* qvd = &Qv[row * QS + doff / 2];
        #pragma unroll
        for (int u = 0; u < 16; u++) {
            float2 f = unpackh2(rw[u]);
            int d = doff + 2 * u;
            qud[u] = packh2(f.x + sub[d], f.y + sub[d + 1]);
            qvd[u] = packh2(f.x + svb[d], f.y + svb[d + 1]);
        }
    }
    cp_wait0();
    __syncthreads();

    score_mma_bf16(Qu, KP, cs, obase, bi, bj, wm, wn, gid, tig);
    __syncthreads();

    #pragma unroll
    for (int l = 0; l < 4; l++) {
        int idx = tid + l * 256;
        int row = idx >> 3, c16 = idx & 7;
        cp16g((char*)KP + row * (QS * 4) + c16 * 16,
              p16 + ((size_t)(b * T + bj + row) * H + h) * DK + c16 * 8);
    }
    cp_commit();
    cp_wait0();
    __syncthreads();

    score_mma_bf16(Qv, KP, ps, obase, bi, bj, wm, wn, gid, tig);
}

// ---------------------------------------------------------------------------
// Fused rel-shift + softmax: bf16 in, fp16 attn out. Block per row (R10 shape),
// 2-sync reduction (separate partial arrays, local 8-way reduce).
//   shifted[i,j] = (j<=i) ? ps[i, T+j-i-1] : (j==i+1) ? 0 : ps[i+1, j-i-2]
// ---------------------------------------------------------------------------
__global__ __launch_bounds__(256) void softmax_shift_kernel(
    const __nv_bfloat16* __restrict__ cs, const __nv_bfloat16* __restrict__ ps,
    __half* __restrict__ attn)
{
    int i  = blockIdx.x;
    int bh = blockIdx.y;
    int tid = threadIdx.x;
    size_t base = (size_t)bh * T * T;
    int j0 = tid * 4;

    ushort4 craw = *(const ushort4*)&cs[base + (size_t)i * T + j0];
    const unsigned short* cw = (const unsigned short*)&craw;

    float vals[4];
    float mx = -3.4e38f;
    #pragma unroll
    for (int l = 0; l < 4; l++) {
        int j = j0 + l;
        float pv;
        if (j <= i)
            pv = bf2f(*(const unsigned short*)&ps[base + (size_t)i * T + (T + j - i - 1)]);
        else if (j == i + 1)
            pv = 0.0f;
        else
            pv = bf2f(*(const unsigned short*)&ps[base + (size_t)(i + 1) * T + (j - i - 2)]);
        float s = bf2f(cw[l]) + pv;
        vals[l] = s;
        mx = fmaxf(mx, s);
    }

    __shared__ float red_m[8], red_s[8];
    #pragma unroll
    for (int o = 16; o > 0; o >>= 1) mx = fmaxf(mx, __shfl_xor_sync(0xffffffffu, mx, o));
    if ((tid & 31) == 0) red_m[tid >> 5] = mx;
    __syncthreads();
    float m0 = red_m[0];
    #pragma unroll
    for (int w = 1; w < 8; w++) m0 = fmaxf(m0, red_m[w]);

    float sum = 0.f;
    #pragma unroll
    for (int l = 0; l < 4; l++) { vals[l] = __expf(vals[l] - m0); sum += vals[l]; }
    #pragma unroll
    for (int o = 16; o > 0; o >>= 1) sum += __shfl_xor_sync(0xffffffffu, sum, o);
    if ((tid & 31) == 0) red_s[tid >> 5] = sum;
    __syncthreads();
    float s0 = red_s[0];
    #pragma unroll
    for (int w = 1; w < 8; w++) s0 += red_s[w];
    float rinv = 1.0f / s0;

    uint2 outp;
    outp.x = packh2(vals[0] * rinv, vals[1] * rinv);
    outp.y = packh2(vals[2] * rinv, vals[3] * rinv);
    *(uint2*)&attn[base + (size_t)i * T + j0] = outp;
}

// ---------------------------------------------------------------------------
// Context (fp16): ctx16 = attn @ v. Block 128x64, 8 warps 4x2, K-step 32, 3-stage.
// ---------------------------------------------------------------------------
__global__ __launch_bounds__(256, 2) void context_f16(
    const __half* __restrict__ attn, const __half* __restrict__ v16i,
    __half* __restrict__ ctx16)
{
    __shared__ unsigned As[3][128 * 20];
    __shared__ unsigned Vs[3][16 * 72];
    int bh = blockIdx.y, b = bh >> 3, h = bh & 7;
    int bm = blockIdx.x * 128;
    int tid = threadIdx.x, warp = tid >> 5, lane = tid & 31;
    int gid = lane >> 2, tig = lane & 3;
    int wm = warp >> 1, wn = warp & 1;
    size_t abase = (size_t)bh * T * T;
    const unsigned* vsrc = (const unsigned*)v16i + (size_t)bh * 512 * 64;

    const int nsteps = T / 32;

    #pragma unroll
    for (int s = 0; s < 2; s++) {
        int k0 = s * 32;
        #pragma unroll
        for (int l = 0; l < 2; l++) {
            int idx = tid + l * 256;
            int row = idx >> 2, c = idx & 3;
            cp16g((char*)As[s] + row * 80 + c * 16,
                  attn + abase + (size_t)(bm + row) * T + k0 + c * 8);
        }
        {
            int kk = tid >> 4, c = tid & 15;
            cp16g((char*)Vs[s] + kk * 288 + c * 16,
                  vsrc + (size_t)(k0 / 2 + kk) * 64 + c * 4);
        }
        cp_commit();
    }

    float acc[2][4][4] = {};
    for (int s = 0; s < nsteps; s++) {
        cp_wait1();
        __syncthreads();
        int st = s % 3;
        if (s + 2 < nsteps) {
            int k0 = (s + 2) * 32, st2 = (s + 2) % 3;
            #pragma unroll
            for (int l = 0; l < 2; l++) {
                int idx = tid + l * 256;
                int row = idx >> 2, c = idx & 3;
                cp16g((char*)As[st2] + row * 80 + c * 16,
                      attn + abase + (size_t)(bm + row) * T + k0 + c * 8);
            }
            int kk = tid >> 4, c = tid & 15;
            cp16g((char*)Vs[st2] + kk * 288 + c * 16,
                  vsrc + (size_t)(k0 / 2 + kk) * 64 + c * 4);
        }
        cp_commit();

        #pragma unroll
        for (int ks = 0; ks < 2; ks++) {
            unsigned af[2][4], bf[4][2];
            #pragma unroll
            for (int mt = 0; mt < 2; mt++) {
                int r = wm * 32 + mt * 16 + gid;
                af[mt][0] = As[st][r * 20 + ks * 8 + tig];
                af[mt][1] = As[st][(r + 8) * 20 + ks * 8 + tig];
                af[mt][2] = As[st][r * 20 + ks * 8 + 4 + tig];
                af[mt][3] = As[st][(r + 8) * 20 + ks * 8 + 4 + tig];
            }
            #pragma unroll
            for (int nt = 0; nt < 4; nt++) {
                int c = wn * 32 + nt * 8 + gid;
                bf[nt][0] = Vs[st][(ks * 8 + tig) * 72 + c];
                bf[nt][1] = Vs[st][(ks * 8 + 4 + tig) * 72 + c];
            }
            #pragma unroll
            for (int mt = 0; mt < 2; mt++)
                #pragma unroll
                for (int nt = 0; nt < 4; nt++)
                    mma_f16(acc[mt][nt], af[mt][0], af[mt][1], af[mt][2], af[mt][3],
                            bf[nt][0], bf[nt][1]);
        }
    }

    #pragma unroll
    for (int mt = 0; mt < 2; mt++) {
        int r0 = bm + wm * 32 + mt * 16 + gid;
        #pragma unroll
        for (int nt = 0; nt < 4; nt++) {
            int c0 = wn * 32 + nt * 8 + 2 * tig;
            *(unsigned*)&ctx16[((size_t)(b * T + r0) * H + h) * DK + c0] =
                packh2(acc[mt][nt][0], acc[mt][nt][1]);
            *(unsigned*)&ctx16[((size_t)(b * T + r0 + 8) * H + h) * DK + c0] =
                packh2(acc[mt][nt][2], acc[mt][nt][3]);
        }
    }
}

// ---------------------------------------------------------------------------
extern "C" void kernel_launch(void* const* d_in, const int* in_sizes, int n_in,
                              void* d_out, int out_size)
{
    const float* query = (const float*)d_in[0];
    const float* key   = (const float*)d_in[1];
    const float* value = (const float*)d_in[2];
    const float* pos   = (const float*)d_in[3];
    const float* Wq = (const float*)d_in[4];
    const float* bq = (const float*)d_in[5];
    const float* Wk = (const float*)d_in[6];
    const float* bk = (const float*)d_in[7];
    const float* Wv = (const float*)d_in[8];
    const float* bv = (const float*)d_in[9];
    const float* Wp = (const float*)d_in[10];
    const float* ub = (const float*)d_in[11];
    const float* vb = (const float*)d_in[12];
    const float* Wo = (const float*)d_in[13];
    const float* bo = (const float*)d_in[14];
    float* out = (float*)d_out;

    __half *x16, *q16, *k16, *v16, *p16, *v16i, *attn16, *ctx16;
    unsigned* w16;
    __nv_bfloat16 *cs, *ps;
    cudaGetSymbolAddress((void**)&x16,    g_x16);
    cudaGetSymbolAddress((void**)&w16,    g_w16);
    cudaGetSymbolAddress((void**)&q16,    g_q16);
    cudaGetSymbolAddress((void**)&k16,    g_k16);
    cudaGetSymbolAddress((void**)&v16,    g_v16);
    cudaGetSymbolAddress((void**)&p16,    g_p16);
    cudaGetSymbolAddress((void**)&v16i,   g_v16i);
    cudaGetSymbolAddress((void**)&cs,     g_cs);
    cudaGetSymbolAddress((void**)&ps,     g_ps);
    cudaGetSymbolAddress((void**)&attn16, g_attn16);
    cudaGetSymbolAddress((void**)&ctx16,  g_ctx16);

    const int SMEM_GEMM  = (3 * 128 * 20 + 3 * 16 * 136) * 4;   // 56832 B
    const int SMEM_SCORE = 3 * 128 * QS * 4;                    // 55296 B
    cudaFuncSetAttribute(gemm_h16,
        cudaFuncAttributeMaxDynamicSharedMemorySize, SMEM_GEMM);
    cudaFuncSetAttribute(score_fused_f16,
        cudaFuncAttributeMaxDynamicSharedMemorySize, SMEM_SCORE);

    // one-time conversions
    ActPtrs ap;
    ap.in[0] = query; ap.in[1] = key; ap.in[2] = value; ap.in[3] = pos;
    ap.out[0] = x16 + 0 * (size_t)BT * D;
    ap.out[1] = x16 + 1 * (size_t)BT * D;
    ap.out[2] = x16 + 2 * (size_t)BT * D;
    ap.out[3] = x16 + 3 * (size_t)BT * D;
    cvt_act<<<dim3(BT * D / (8 * 256), 4), 256>>>(ap);

    WPtrs wp;
    wp.in[0] = Wq; wp.in[1] = Wk; wp.in[2] = Wv; wp.in[3] = Wp; wp.in[4] = Wo;
    for (int i = 0; i < 5; i++) wp.out[i] = w16 + (size_t)i * (D * D / 2);
    cvt_w<<<dim3(128, 5), 256>>>(wp);

    // GEMMs
    GArgs ga;
    ga.A[0] = ap.out[0]; ga.A[1] = ap.out[1]; ga.A[2] = ap.out[2]; ga.A[3] = ap.out[3];
    ga.A[4] = ctx16;
    for (int i = 0; i < 5; i++) ga.W[i] = wp.out[i];
    ga.bias[0] = bq; ga.bias[1] = bk; ga.bias[2] = bv; ga.bias[3] = nullptr; ga.bias[4] = bo;
    ga.Ch[0] = q16; ga.Ch[1] = k16; ga.Ch[2] = v16; ga.Ch[3] = p16; ga.Ch[4] = nullptr;
    ga.Cf[0] = ga.Cf[1] = ga.Cf[2] = ga.Cf[3] = nullptr; ga.Cf[4] = out;

    dim3 gproj(D / 128, BT / 128, 4);       // (4, 64, 4)
    gemm_h16<<<gproj, 256, SMEM_GEMM>>>(ga, 0);

    v_reshape<<<1024, 256>>>(v16, v16i);

    dim3 gsc(T / 128, T / 128, B * H);      // (8, 8, 64)
    score_fused_f16<<<gsc, 256, SMEM_SCORE>>>(q16, k16, p16, ub, vb, cs, ps);

    dim3 gsm(T, B * H);                     // (1024, 64)
    softmax_shift_kernel<<<gsm, 256>>>(cs, ps, attn16);

    dim3 gctx(T / 128, B * H);              // (8, 64)
    context_f16<<<gctx, 256>>>(attn16, v16i, ctx16);

    dim3 gout(D / 128, BT / 128, 1);        // (4, 64)
    gemm_h16<<<gout, 256, SMEM_GEMM>>>(ga, 4);
}